// round 1
// baseline (speedup 1.0000x reference)
#include <cuda_runtime.h>
#include <math.h>

// Problem constants (fixed by the reference)
#define BB 4096
#define TT 200
#define CC 38
#define SS 30
#define KSHIFT 2.0f

// Scratch (no cudaMalloc allowed)
__device__ float g_ctc[BB];
__device__ float g_kl[BB * SS];

__device__ __forceinline__ float warp_sum(float v) {
#pragma unroll
    for (int o = 16; o > 0; o >>= 1) v += __shfl_xor_sync(0xffffffffu, v, o);
    return v;
}

// ---------------------------------------------------------------------------
// CTC forward: one warp per batch item.
// Lane i holds alpha[2i] (even/blank state, i<=30) and alpha[2i+1] (odd/label
// state, i<=29) as fp64. Emissions are exp(x - K) (unnormalized, shifted);
// the softmax denominator is handled analytically via sumLogD.
// ---------------------------------------------------------------------------
__global__ void __launch_bounds__(256) ctc_kernel(
    const float* __restrict__ x,
    const int* __restrict__ target,
    const int* __restrict__ ilen,
    const int* __restrict__ tlen)
{
    __shared__ float erow_s[8][40];   // per-warp e-row (38 used, padded)
    const int warp = threadIdx.x >> 5;
    const int lane = threadIdx.x & 31;
    const int b = blockIdx.x * 8 + warp;
    float* erow = erow_s[warp];

    // Labels: lane s holds target[b][s] (s < 30)
    int tg  = (lane < SS) ? target[b * SS + lane] : 1;
    int tgp = __shfl_up_sync(0xffffffffu, tg, 1);
    // allow_skip for odd state 2s+1: label != previous label (s=0: true, but
    // its alpha[-1] input is forced to 0 via the shfl boundary anyway)
    const bool skip = (lane == 0) ? true : (tg != tgp);

    const int il = ilen[b];
    const int tl = tlen[b];

    double ae = (lane == 0) ? 1.0 : 0.0;  // alpha[2*lane]
    double ao = 0.0;                      // alpha[2*lane+1]
    double sumLogD = 0.0;

    const float* row = x + (size_t)b * TT * CC;

    // Prefetch row t=0
    float x1 = row[lane];
    float x2 = (lane < 6) ? row[32 + lane] : -1e30f;

    for (int t = 0; t < il; ++t) {
        float e1 = __expf(x1 - KSHIFT);
        float e2 = (lane < 6) ? __expf(x2 - KSHIFT) : 0.0f;
        erow[lane] = e1;
        if (lane < 6) erow[32 + lane] = e2;
        __syncwarp();

        // Prefetch next row while this step computes
        if (t + 1 < il) {
            const float* nr = row + (size_t)(t + 1) * CC;
            x1 = nr[lane];
            x2 = (lane < 6) ? nr[32 + lane] : -1e30f;
        }

        // Shifted softmax denominator (off the alpha critical path)
        float D = warp_sum(e1 + e2);
        sumLogD += (double)__logf(D);

        float pb = erow[0];    // blank emission
        float pl = erow[tg];   // label emission for this lane's odd state

        double op = __shfl_up_sync(0xffffffffu, ao, 1);  // alpha[2*lane-1]
        if (lane == 0) op = 0.0;

        double ne = (ae + op) * (double)pb;                         // even
        double no = (ao + ae + (skip ? op : 0.0)) * (double)pl;     // odd
        ae = (lane <= 30) ? ne : 0.0;
        ao = (lane < 30) ? no : 0.0;
        __syncwarp();  // protect erow before next iteration's writes
    }

    // nll = -( log(alpha[2*tl] + alpha[2*tl-1]) - sumLogD )   (K cancels)
    double aev = __shfl_sync(0xffffffffu, ae, tl);       // state 2*tl (even)
    double aov = __shfl_sync(0xffffffffu, ao, tl - 1);   // state 2*tl-1 (odd)
    if (lane == 0) {
        double s = aev + aov;
        float nll;
        if (!(s > 0.0)) {
            nll = 0.0f;                          // zero_infinity
        } else {
            double lg = log(s) - sumLogD;        // fp64 log: full range
            nll = (float)(-lg);
            if (nll > 1e8f) nll = 0.0f;          // zero_infinity threshold
        }
        g_ctc[b] = nll / (float)tl;
    }
}

// ---------------------------------------------------------------------------
// KL smoothing: one warp per (b, s) aligned row.
//   pred_c = x_c - lse ;  SLS_c = ms[f-1][tg-1][c-1] (c>=1), SLS_0 = 0
//   g_kl[b,s] = (sum_c SLS_c) * mean_c( t_c * (log t_c - pred_c) ),  t=SLS+1e-10
// ---------------------------------------------------------------------------
__global__ void __launch_bounds__(256) kl_kernel(
    const float* __restrict__ x,
    const int* __restrict__ target,
    const int* __restrict__ tlen,
    const int* __restrict__ pos,
    const float* __restrict__ ms)
{
    const int warp = threadIdx.x >> 5;
    const int lane = threadIdx.x & 31;
    const int idx = blockIdx.x * 8 + warp;   // 0 .. B*S-1
    const int b = idx / SS;
    const int s = idx - b * SS;

    const int tl = tlen[b];
    if (s >= tl) {                           // masked-out aligned row
        if (lane == 0) g_kl[idx] = 0.0f;
        return;
    }

    const int p  = pos[b * SS + s];
    const int tg = target[b * SS + s];
    const int f  = (s == 0) ? (CC - 1) : target[b * SS + s - 1];

    const float* row = x + ((size_t)b * TT + p) * CC;
    float x1 = row[lane];
    float x2 = (lane < 6) ? row[32 + lane] : 0.0f;
    float e1 = __expf(x1);
    float e2 = (lane < 6) ? __expf(x2) : 0.0f;
    float lse = __logf(warp_sum(e1 + e2));

    const float* msr = ms + ((size_t)(f - 1) * 37 + (tg - 1)) * 37;
    float s1 = (lane >= 1) ? msr[lane - 1] : 0.0f;   // class c = lane
    float s2 = (lane < 6) ? msr[lane + 31] : 0.0f;   // class c = lane + 32

    float t1 = s1 + 1e-10f;
    float term = t1 * (__logf(t1) - (x1 - lse));
    float wp = s1;
    if (lane < 6) {
        float t2 = s2 + 1e-10f;
        term += t2 * (__logf(t2) - (x2 - lse));
        wp += s2;
    }
    float tsum = warp_sum(term);
    float wsum = warp_sum(wp);
    if (lane == 0) g_kl[idx] = wsum * (tsum * (1.0f / (float)CC));
}

// ---------------------------------------------------------------------------
// Deterministic final reduction:
//   out = mean_b( nll_b / tl_b )  +  sum_b smoothing_b * (sum_s kl[b,s]) / tl_b
//   smoothing_b = 1 - 0.95^(1/tl_b)
// ---------------------------------------------------------------------------
__global__ void __launch_bounds__(1024) reduce_kernel(
    const int* __restrict__ tlen, float* __restrict__ out)
{
    __shared__ double sm[1024];
    const int tid = threadIdx.x;
    double acc = 0.0;
    for (int b = tid; b < BB; b += 1024) {
        double L = (double)tlen[b];
        double klb = 0.0;
#pragma unroll
        for (int s = 0; s < SS; ++s) klb += (double)g_kl[b * SS + s];
        double per = klb / L;
        double smooth = 1.0 - pow(0.95, 1.0 / L);
        acc += (double)g_ctc[b] * (1.0 / (double)BB) + smooth * per;
    }
    sm[tid] = acc;
    __syncthreads();
    for (int st = 512; st > 0; st >>= 1) {
        if (tid < st) sm[tid] += sm[tid + st];
        __syncthreads();
    }
    if (tid == 0) out[0] = (float)sm[0];
}

// ---------------------------------------------------------------------------
extern "C" void kernel_launch(void* const* d_in, const int* in_sizes, int n_in,
                              void* d_out, int out_size)
{
    const float* x      = (const float*)d_in[0];   // [B,T,C] f32
    const int*   target = (const int*)d_in[1];     // [B,S]   i32
    const int*   ilen   = (const int*)d_in[2];     // [B]     i32
    const int*   tlen   = (const int*)d_in[3];     // [B]     i32
    const int*   pos    = (const int*)d_in[4];     // [B,S]   i32
    const float* ms     = (const float*)d_in[5];   // [37,37,37] f32

    ctc_kernel<<<BB / 8, 256>>>(x, target, ilen, tlen);
    kl_kernel<<<(BB * SS) / 8, 256>>>(x, target, tlen, pos, ms);
    reduce_kernel<<<1, 1024>>>(tlen, (float*)d_out);
}

// round 4
// speedup vs baseline: 1.0517x; 1.0517x over previous
#include <cuda_runtime.h>
#include <math.h>

// Problem constants (fixed by the reference)
#define BB 4096
#define TT 200
#define CC 38
#define SS 30
#define FULLMASK 0xffffffffu
#define CTC_BLOCKS 512            // BB/8 warps-per-block
#define KL_BLOCKS  15360          // BB*SS/8
#define R1_BLOCKS  240
#define LN2 0.6931471805599453

// Scratch (no cudaMalloc allowed)
__device__ float  g_ctc[BB];
__device__ float  g_kl[BB * SS];
__device__ double g_part[R1_BLOCKS];

__device__ __forceinline__ float warp_sum(float v) {
#pragma unroll
    for (int o = 16; o > 0; o >>= 1) v += __shfl_xor_sync(FULLMASK, v, o);
    return v;
}
__device__ __forceinline__ float warp_max(float v) {
#pragma unroll
    for (int o = 16; o > 0; o >>= 1) v = fmaxf(v, __shfl_xor_sync(FULLMASK, v, o));
    return v;
}

// ---------------------------------------------------------------------------
// fp64 fallback (R1-proven numerics): rerun one sample's full CTC forward.
// Only taken by warps whose fp32 pass underflowed. Whole warp participates.
// ---------------------------------------------------------------------------
__device__ __noinline__ float ctc_fp64(
    const float* __restrict__ row, int tg, int tgB, bool hi, bool skip,
    int il, int tl)
{
    const int lane = threadIdx.x & 31;
    double ae = (lane == 0) ? 1.0 : 0.0;
    double ao = 0.0;
    double sumLogD = 0.0;

    for (int t = 0; t < il; ++t) {
        float x1 = row[(size_t)t * CC + lane];
        float x2 = (lane < 6) ? row[(size_t)t * CC + 32 + lane] : -1e30f;
        float e1 = __expf(x1 - 2.0f);
        float e2 = __expf(x2 - 2.0f);
        float D  = warp_sum(e1 + e2);
        sumLogD += (double)__logf(D);
        float pb  = __shfl_sync(FULLMASK, e1, 0);
        float plA = __shfl_sync(FULLMASK, e1, tg);
        float plB = __shfl_sync(FULLMASK, e2, tgB);
        float pl  = hi ? plB : plA;
        double op = __shfl_up_sync(FULLMASK, ao, 1);
        if (lane == 0) op = 0.0;
        double ne = (ae + op) * (double)pb;
        double no = (ao + ae + (skip ? op : 0.0)) * (double)pl;
        ae = (lane <= 30) ? ne : 0.0;
        ao = (lane < 30) ? no : 0.0;
    }
    double aev = __shfl_sync(FULLMASK, ae, tl);
    double aov = __shfl_sync(FULLMASK, ao, tl - 1);
    double s = aev + aov;
    float nll = 0.0f;
    if (s > 0.0) {
        double lg = log(s) - sumLogD;
        nll = (float)(-lg);
        if (nll > 1e8f) nll = 0.0f;
    }
    return nll;
}

// ---------------------------------------------------------------------------
// CTC forward, one warp per batch item, fp32 alpha + exponent renorm to 2^96.
// Lane i holds alpha[2i] (blank state) and alpha[2i+1] (label state).
// Emissions are unnormalized exp(x-2); softmax denominators handled
// analytically via sum of log2(D_t); the shift K=2 cancels identically.
// Underflow-suspect warps (final sum < 2^-60 stored) redo in fp64.
// ---------------------------------------------------------------------------
__device__ __forceinline__ void ctc_body(
    const float* __restrict__ x, const int* __restrict__ target,
    const int* __restrict__ ilen, const int* __restrict__ tlen, int b)
{
    const int lane = threadIdx.x & 31;

    int tg  = (lane < SS) ? target[b * SS + lane] : 1;
    int tgp = __shfl_up_sync(FULLMASK, tg, 1);
    const bool  skip  = (lane == 0 || tg != tgp);
    const float skipf = skip ? 1.0f : 0.0f;
    const bool  hi    = tg >= 32;
    const int   tgB   = tg - 32;

    const int il = ilen[b];
    const int tl = tlen[b];

    float ae = (lane == 0) ? 1.0f : 0.0f;
    float ao = 0.0f;
    float sumL2 = 0.0f;      // Kahan-compensated sum of log2(D_t)
    float sumC  = 0.0f;
    int   Esum  = 0;         // shed binary exponent (true = stored * 2^Esum)

    const float* row = x + (size_t)b * TT * CC;

    auto step = [&](float x1, float x2) {
        float e1 = __expf(x1 - 2.0f);
        float e2 = __expf(x2 - 2.0f);          // lanes>=6 fed -1e30 -> 0
        float D  = warp_sum(e1 + e2);
        {   // Kahan
            float y = __log2f(D) - sumC;
            float t = sumL2 + y;
            sumC = (t - sumL2) - y;
            sumL2 = t;
        }
        float pb  = __shfl_sync(FULLMASK, e1, 0);
        float plA = __shfl_sync(FULLMASK, e1, tg);
        float plB = __shfl_sync(FULLMASK, e2, tgB);
        float pl  = hi ? plB : plA;
        float op  = __shfl_up_sync(FULLMASK, ao, 1);
        if (lane == 0) op = 0.0f;
        float s  = ae + op;
        float ne = s * pb;
        float u  = (skip ? s : ae) + ao;       // = ao + ae + skip*op
        float no = u * pl;
        ae = ne; ao = no;
        (void)skipf;
    };
    auto renorm = [&]() {
        float M = warp_max(fmaxf(ae, ao));
        unsigned mb = __float_as_uint(M);
        if (mb >= (96u << 23)) {               // e >= -31, M normal
            int e = (int)((mb >> 23) & 0xff) - 127;
            float sc = __uint_as_float((unsigned)(223 - e) << 23);  // 2^(96-e)
            ae *= sc; ao *= sc;
            Esum += e - 96;
        }
    };

    if (il == TT) {
        // Fixed-trip path with one-group-ahead register prefetch.
        float cx1[4], cx2[4];
#pragma unroll
        for (int i = 0; i < 4; ++i) {
            cx1[i] = row[i * CC + lane];
            cx2[i] = (lane < 6) ? row[i * CC + 32 + lane] : -1e30f;
        }
        for (int g = 0; g < TT / 4; ++g) {
            float nx1[4], nx2[4];
#pragma unroll
            for (int i = 0; i < 4; ++i) { nx1[i] = -1e30f; nx2[i] = -1e30f; }
            if (g + 1 < TT / 4) {
                const float* np = row + (size_t)(g + 1) * 4 * CC;
#pragma unroll
                for (int i = 0; i < 4; ++i) {
                    nx1[i] = np[i * CC + lane];
                    nx2[i] = (lane < 6) ? np[i * CC + 32 + lane] : -1e30f;
                }
            }
#pragma unroll
            for (int i = 0; i < 4; ++i) step(cx1[i], cx2[i]);
            renorm();
#pragma unroll
            for (int i = 0; i < 4; ++i) { cx1[i] = nx1[i]; cx2[i] = nx2[i]; }
        }
    } else {
        for (int t = 0; t < il; ++t) {
            float x1 = row[(size_t)t * CC + lane];
            float x2 = (lane < 6) ? row[(size_t)t * CC + 32 + lane] : -1e30f;
            step(x1, x2);
            if ((t & 3) == 3) renorm();
        }
    }

    // All lanes get the end-state values (shfl broadcasts) -> uniform branch.
    float aev = __shfl_sync(FULLMASK, ae, tl);       // state 2*tl
    float aov = __shfl_sync(FULLMASK, ao, tl - 1);   // state 2*tl-1
    double ssum = (double)aev + (double)aov;

    // Accept only if comfortably above the flush floor (2^-60 stored units:
    // any flushed contribution is >= 2^85 smaller -> provably negligible).
    if (ssum >= 8.673617379884035e-19 /* 2^-60 */) {
        if (lane == 0) {
            double lg = log(ssum) + ((double)Esum - (double)sumL2) * LN2;
            float nll = (float)(-lg);
            if (nll > 1e8f) nll = 0.0f;              // zero_infinity
            g_ctc[b] = nll / (float)tl;
        }
    } else {
        // Rare: fp32 window insufficient for this sample -> exact fp64 redo.
        float nll = ctc_fp64(row, tg, tgB, hi, skip, il, tl);
        if (lane == 0) g_ctc[b] = nll / (float)tl;
    }
}

// ---------------------------------------------------------------------------
// KL smoothing, one warp per (b, s); result pre-scaled by smoothing_b / L_b.
// ---------------------------------------------------------------------------
__device__ __forceinline__ void kl_body(
    const float* __restrict__ x, const int* __restrict__ target,
    const int* __restrict__ tlen, const int* __restrict__ pos,
    const float* __restrict__ ms, int idx)
{
    const int lane = threadIdx.x & 31;
    const int b = idx / SS;
    const int s = idx - b * SS;

    const int tl = tlen[b];
    if (s >= tl) {
        if (lane == 0) g_kl[idx] = 0.0f;
        return;
    }
    const int p  = pos[b * SS + s];
    const int tg = target[b * SS + s];
    const int f  = (s == 0) ? (CC - 1) : target[b * SS + s - 1];

    const float* row = x + ((size_t)b * TT + p) * CC;
    float x1 = row[lane];
    float x2 = (lane < 6) ? row[32 + lane] : 0.0f;
    float e1 = __expf(x1);
    float e2 = (lane < 6) ? __expf(x2) : 0.0f;
    float lse = __logf(warp_sum(e1 + e2));

    const float* msr = ms + ((size_t)(f - 1) * 37 + (tg - 1)) * 37;
    float s1 = (lane >= 1) ? msr[lane - 1] : 0.0f;   // class c = lane
    float s2 = (lane < 6) ? msr[lane + 31] : 0.0f;   // class c = lane + 32

    float t1 = s1 + 1e-10f;
    float term = t1 * (__logf(t1) - (x1 - lse));
    float wp = s1;
    if (lane < 6) {
        float t2 = s2 + 1e-10f;
        term += t2 * (__logf(t2) - (x2 - lse));
        wp += s2;
    }
    float tsum = warp_sum(term);
    float wsum = warp_sum(wp);
    if (lane == 0) {
        float L = (float)tl;
        float smooth = -expm1f(-0.05129329438755058f / L);  // 1 - 0.95^(1/L)
        g_kl[idx] = (smooth / L) * (wsum * tsum * (1.0f / (float)CC));
    }
}

// ---------------------------------------------------------------------------
// Fused launch: blocks [0,512) run CTC (latency-bound); the rest run KL and
// backfill issue bubbles.
// ---------------------------------------------------------------------------
__global__ void __launch_bounds__(256) fused_kernel(
    const float* __restrict__ x, const int* __restrict__ target,
    const int* __restrict__ ilen, const int* __restrict__ tlen,
    const int* __restrict__ pos, const float* __restrict__ ms)
{
    const int warp = threadIdx.x >> 5;
    if (blockIdx.x < CTC_BLOCKS) {
        ctc_body(x, target, ilen, tlen, blockIdx.x * 8 + warp);
    } else {
        kl_body(x, target, tlen, pos, ms, (blockIdx.x - CTC_BLOCKS) * 8 + warp);
    }
}

// ---------------------------------------------------------------------------
// Deterministic two-stage reduction.
// ---------------------------------------------------------------------------
__global__ void __launch_bounds__(256) reduce1_kernel()
{
    __shared__ double sm[256];
    const int tid = threadIdx.x;
    double acc = 0.0;
    for (int i = blockIdx.x * 256 + tid; i < BB * SS; i += R1_BLOCKS * 256)
        acc += (double)g_kl[i];
    for (int i = blockIdx.x * 256 + tid; i < BB; i += R1_BLOCKS * 256)
        acc += (double)g_ctc[i] * (1.0 / (double)BB);
    sm[tid] = acc;
    __syncthreads();
    for (int st = 128; st > 0; st >>= 1) {
        if (tid < st) sm[tid] += sm[tid + st];
        __syncthreads();
    }
    if (tid == 0) g_part[blockIdx.x] = sm[0];
}

__global__ void __launch_bounds__(256) reduce2_kernel(float* __restrict__ out)
{
    __shared__ double sm[256];
    const int tid = threadIdx.x;
    sm[tid] = (tid < R1_BLOCKS) ? g_part[tid] : 0.0;
    __syncthreads();
    for (int st = 128; st > 0; st >>= 1) {
        if (tid < st) sm[tid] += sm[tid + st];
        __syncthreads();
    }
    if (tid == 0) out[0] = (float)sm[0];
}

// ---------------------------------------------------------------------------
extern "C" void kernel_launch(void* const* d_in, const int* in_sizes, int n_in,
                              void* d_out, int out_size)
{
    const float* x      = (const float*)d_in[0];   // [B,T,C] f32
    const int*   target = (const int*)d_in[1];     // [B,S]   i32
    const int*   ilen   = (const int*)d_in[2];     // [B]     i32
    const int*   tlen   = (const int*)d_in[3];     // [B]     i32
    const int*   pos    = (const int*)d_in[4];     // [B,S]   i32
    const float* ms     = (const float*)d_in[5];   // [37,37,37] f32

    fused_kernel<<<CTC_BLOCKS + KL_BLOCKS, 256>>>(x, target, ilen, tlen, pos, ms);
    reduce1_kernel<<<R1_BLOCKS, 256>>>();
    reduce2_kernel<<<1, 256>>>((float*)d_out);
}

// round 6
// speedup vs baseline: 1.2772x; 1.2144x over previous
#include <cuda_runtime.h>
#include <math.h>

// Problem constants (fixed by the reference)
#define BB 4096
#define TT 200
#define CC 38
#define SS 30
#define FULLMASK 0xffffffffu
#define D_BLOCKS   1024           // 8192 warps = 2 per sample (100 rows each)
#define KL_BLOCKS  15360          // BB*SS/8
#define CTC_BLOCKS 512            // 4096 warps = 1 per sample
#define R1_BLOCKS  240
#define LN2 0.6931471805599453

// Scratch (no cudaMalloc allowed)
__device__ float  g_ctc[BB];
__device__ float  g_kl[BB * SS];
__device__ double g_d2[BB * 2];   // per-(b,half) sum of log2(D_t)
__device__ double g_part[R1_BLOCKS];

__device__ __forceinline__ float warp_sum(float v) {
#pragma unroll
    for (int o = 16; o > 0; o >>= 1) v += __shfl_xor_sync(FULLMASK, v, o);
    return v;
}
__device__ __forceinline__ float warp_max(float v) {
#pragma unroll
    for (int o = 16; o > 0; o >>= 1) v = fmaxf(v, __shfl_xor_sync(FULLMASK, v, o));
    return v;
}

// ---------------------------------------------------------------------------
// Kernel 1a: softmax-denominator pass. Warp w handles sample b = w/2,
// rows [h*100, h*100+100), h = w%2. Accumulates sum of log2(sum_c exp(x-2)).
// Fully parallel: the 5-shfl row reduction has no serial dependency.
// ---------------------------------------------------------------------------
__device__ __forceinline__ void d_body(
    const float* __restrict__ x, const int* __restrict__ ilen, int w)
{
    const int lane = threadIdx.x & 31;
    const int b = w >> 1;
    const int h = w & 1;
    const int t0 = h * 100;
    const int il = ilen[b];
    const int tend = (il < t0 + 100) ? il : (t0 + 100);

    const float* xp = x + (size_t)b * TT * CC;
    float sumL2 = 0.0f, sumC = 0.0f;

    int t = t0;
    // two rows per iteration for load/MUFU ILP
    for (; t + 2 <= tend; t += 2) {
        const float* r0 = xp + (size_t)t * CC;
        const float* r1 = r0 + CC;
        float a1 = r0[lane];
        float a2 = (lane < 6) ? r0[32 + lane] : -1e30f;
        float b1 = r1[lane];
        float b2 = (lane < 6) ? r1[32 + lane] : -1e30f;
        float ea = __expf(a1 - 2.0f) + __expf(a2 - 2.0f);
        float eb = __expf(b1 - 2.0f) + __expf(b2 - 2.0f);
        float Da = warp_sum(ea);
        float Db = warp_sum(eb);
        float y = (__log2f(Da) + __log2f(Db)) - sumC;
        float s = sumL2 + y;
        sumC = (s - sumL2) - y;
        sumL2 = s;
    }
    for (; t < tend; ++t) {
        const float* r0 = xp + (size_t)t * CC;
        float a1 = r0[lane];
        float a2 = (lane < 6) ? r0[32 + lane] : -1e30f;
        float D = warp_sum(__expf(a1 - 2.0f) + __expf(a2 - 2.0f));
        float y = __log2f(D) - sumC;
        float s = sumL2 + y;
        sumC = (s - sumL2) - y;
        sumL2 = s;
    }
    if (lane == 0) g_d2[w] = (double)sumL2 - (double)sumC;
}

// ---------------------------------------------------------------------------
// Kernel 1b: KL smoothing, one warp per (b, s); pre-scaled by smoothing_b/L_b.
// ---------------------------------------------------------------------------
__device__ __forceinline__ void kl_body(
    const float* __restrict__ x, const int* __restrict__ target,
    const int* __restrict__ tlen, const int* __restrict__ pos,
    const float* __restrict__ ms, int idx)
{
    const int lane = threadIdx.x & 31;
    const int b = idx / SS;
    const int s = idx - b * SS;

    const int tl = tlen[b];
    if (s >= tl) {
        if (lane == 0) g_kl[idx] = 0.0f;
        return;
    }
    const int p  = pos[b * SS + s];
    const int tg = target[b * SS + s];
    const int f  = (s == 0) ? (CC - 1) : target[b * SS + s - 1];

    const float* row = x + ((size_t)b * TT + p) * CC;
    float x1 = row[lane];
    float x2 = (lane < 6) ? row[32 + lane] : 0.0f;
    float e1 = __expf(x1);
    float e2 = (lane < 6) ? __expf(x2) : 0.0f;
    float lse = __logf(warp_sum(e1 + e2));

    const float* msr = ms + ((size_t)(f - 1) * 37 + (tg - 1)) * 37;
    float s1 = (lane >= 1) ? msr[lane - 1] : 0.0f;   // class c = lane
    float s2 = (lane < 6) ? msr[lane + 31] : 0.0f;   // class c = lane + 32

    float t1 = s1 + 1e-10f;
    float term = t1 * (__logf(t1) - (x1 - lse));
    float wp = s1;
    if (lane < 6) {
        float t2 = s2 + 1e-10f;
        term += t2 * (__logf(t2) - (x2 - lse));
        wp += s2;
    }
    float tsum = warp_sum(term);
    float wsum = warp_sum(wp);
    if (lane == 0) {
        float L = (float)tl;
        float smooth = -expm1f(-0.05129329438755058f / L);  // 1 - 0.95^(1/L)
        g_kl[idx] = (smooth / L) * (wsum * tsum * (1.0f / (float)CC));
    }
}

__global__ void __launch_bounds__(256) pass1_kernel(
    const float* __restrict__ x, const int* __restrict__ target,
    const int* __restrict__ ilen, const int* __restrict__ tlen,
    const int* __restrict__ pos, const float* __restrict__ ms)
{
    const int warp = threadIdx.x >> 5;
    if (blockIdx.x < D_BLOCKS) {
        d_body(x, ilen, blockIdx.x * 8 + warp);
    } else {
        kl_body(x, target, tlen, pos, ms, (blockIdx.x - D_BLOCKS) * 8 + warp);
    }
}

// ---------------------------------------------------------------------------
// fp64 fallback for underflowed samples (rare). Uses precomputed sumLogD.
// ---------------------------------------------------------------------------
__device__ __noinline__ float ctc_fp64(
    const float* __restrict__ xp, int tg, bool skip, int il, int tl,
    double sumLogD)
{
    const int lane = threadIdx.x & 31;
    double ae = (lane == 0) ? 1.0 : 0.0;
    double ao = 0.0;
    for (int t = 0; t < il; ++t) {
        const float* r = xp + (size_t)t * CC;
        float pbe = __expf(r[0] - 2.0f);
        float ple = __expf(r[tg] - 2.0f);
        double op = __shfl_up_sync(FULLMASK, ao, 1);
        if (lane == 0) op = 0.0;
        double ne = (ae + op) * (double)pbe;
        double no = (ao + ae + (skip ? op : 0.0)) * (double)ple;
        ae = (lane <= 30) ? ne : 0.0;
        ao = (lane < 30) ? no : 0.0;
    }
    double aev = __shfl_sync(FULLMASK, ae, tl);
    double aov = __shfl_sync(FULLMASK, ao, tl - 1);
    double s = aev + aov;
    float nll = 0.0f;
    if (s > 0.0) {
        double lg = log(s) - sumLogD;
        nll = (float)(-lg);
        if (nll > 1e8f) nll = 0.0f;
    }
    return nll;
}

// ---------------------------------------------------------------------------
// Kernel 2: CTC recursion, one warp per sample. Lane i holds alpha[2i]
// (blank) and alpha[2i+1] (label 'tg'). Per step: lane-direct emission loads
// (blank = uniform broadcast, label = in-row gather), ONE shfl_up, fp32 alpha
// with exponent renorm to 2^96. D-normalization folded in analytically from
// g_d2. Underflow-suspect warps redo in fp64.
// ---------------------------------------------------------------------------
__global__ void __launch_bounds__(256) ctc_kernel(
    const float* __restrict__ x, const int* __restrict__ target,
    const int* __restrict__ ilen, const int* __restrict__ tlen)
{
    const int lane = threadIdx.x & 31;
    const int b = blockIdx.x * 8 + (threadIdx.x >> 5);

    int tg  = (lane < SS) ? target[b * SS + lane] : 1;
    int tgp = __shfl_up_sync(FULLMASK, tg, 1);
    const bool skip = (lane == 0 || tg != tgp);

    const int il = ilen[b];
    const int tl = tlen[b];
    const double sumLogD = (g_d2[2 * b] + g_d2[2 * b + 1]) * LN2;

    const float* xp = x + (size_t)b * TT * CC;

    float ae = (lane == 0) ? 1.0f : 0.0f;
    float ao = 0.0f;
    int   Esum = 0;                     // true alpha = stored * 2^Esum

    auto step = [&](float pbraw, float plraw) {
        float pbe = __expf(pbraw - 2.0f);
        float ple = __expf(plraw - 2.0f);
        float op  = __shfl_up_sync(FULLMASK, ao, 1);
        if (lane == 0) op = 0.0f;
        float s  = ae + op;
        float ne = s * pbe;
        float u  = (skip ? s : ae) + ao;      // = ao + ae + skip*op
        ae = ne;
        ao = u * ple;
    };
    auto renorm = [&]() {
        float M = warp_max(fmaxf(ae, ao));
        unsigned mb = __float_as_uint(M);
        if (mb >= (96u << 23)) {              // M normal, exponent >= -31
            int e = (int)((mb >> 23) & 0xff) - 127;
            float sc = __uint_as_float((unsigned)(223 - e) << 23);  // 2^(96-e)
            ae *= sc; ao *= sc;
            Esum += e - 96;
        }
    };

    if (il == TT) {
        // 8-step groups, one group of loads in flight ahead (16 loads MLP).
        float cpb[8], cpl[8];
#pragma unroll
        for (int i = 0; i < 8; ++i) {
            cpb[i] = xp[i * CC];
            cpl[i] = xp[i * CC + tg];
        }
        for (int g = 0; g < TT / 8; ++g) {
            float npb[8], npl[8];
            if (g + 1 < TT / 8) {
                const float* np = xp + (size_t)(g + 1) * 8 * CC;
#pragma unroll
                for (int i = 0; i < 8; ++i) {
                    npb[i] = np[i * CC];
                    npl[i] = np[i * CC + tg];
                }
            } else {
#pragma unroll
                for (int i = 0; i < 8; ++i) { npb[i] = 0.0f; npl[i] = 0.0f; }
            }
#pragma unroll
            for (int i = 0; i < 8; ++i) {
                step(cpb[i], cpl[i]);
                if (i == 3 || i == 7) renorm();
            }
#pragma unroll
            for (int i = 0; i < 8; ++i) { cpb[i] = npb[i]; cpl[i] = npl[i]; }
        }
    } else {
        for (int t = 0; t < il; ++t) {
            const float* r = xp + (size_t)t * CC;
            step(r[0], r[tg]);
            if ((t & 3) == 3) renorm();
        }
    }

    // All lanes see the end states (shfl broadcast) -> warp-uniform branch.
    float aev = __shfl_sync(FULLMASK, ae, tl);       // state 2*tl
    float aov = __shfl_sync(FULLMASK, ao, tl - 1);   // state 2*tl-1
    double ssum = (double)aev + (double)aov;

    if (ssum >= 8.673617379884035e-19 /* 2^-60 stored units */) {
        if (lane == 0) {
            double lg = log(ssum) + (double)Esum * LN2 - sumLogD;
            float nll = (float)(-lg);
            if (nll > 1e8f) nll = 0.0f;              // zero_infinity
            g_ctc[b] = nll / (float)tl;
        }
    } else {
        float nll = ctc_fp64(xp, tg, skip, il, tl, sumLogD);
        if (lane == 0) g_ctc[b] = nll / (float)tl;
    }
}

// ---------------------------------------------------------------------------
// Deterministic two-stage reduction.
// ---------------------------------------------------------------------------
__global__ void __launch_bounds__(256) reduce1_kernel()
{
    __shared__ double sm[256];
    const int tid = threadIdx.x;
    double acc = 0.0;
    for (int i = blockIdx.x * 256 + tid; i < BB * SS; i += R1_BLOCKS * 256)
        acc += (double)g_kl[i];
    for (int i = blockIdx.x * 256 + tid; i < BB; i += R1_BLOCKS * 256)
        acc += (double)g_ctc[i] * (1.0 / (double)BB);
    sm[tid] = acc;
    __syncthreads();
    for (int st = 128; st > 0; st >>= 1) {
        if (tid < st) sm[tid] += sm[tid + st];
        __syncthreads();
    }
    if (tid == 0) g_part[blockIdx.x] = sm[0];
}

__global__ void __launch_bounds__(256) reduce2_kernel(float* __restrict__ out)
{
    __shared__ double sm[256];
    const int tid = threadIdx.x;
    sm[tid] = (tid < R1_BLOCKS) ? g_part[tid] : 0.0;
    __syncthreads();
    for (int st = 128; st > 0; st >>= 1) {
        if (tid < st) sm[tid] += sm[tid + st];
        __syncthreads();
    }
    if (tid == 0) out[0] = (float)sm[0];
}

// ---------------------------------------------------------------------------
extern "C" void kernel_launch(void* const* d_in, const int* in_sizes, int n_in,
                              void* d_out, int out_size)
{
    const float* x      = (const float*)d_in[0];   // [B,T,C] f32
    const int*   target = (const int*)d_in[1];     // [B,S]   i32
    const int*   ilen   = (const int*)d_in[2];     // [B]     i32
    const int*   tlen   = (const int*)d_in[3];     // [B]     i32
    const int*   pos    = (const int*)d_in[4];     // [B,S]   i32
    const float* ms     = (const float*)d_in[5];   // [37,37,37] f32

    pass1_kernel<<<D_BLOCKS + KL_BLOCKS, 256>>>(x, target, ilen, tlen, pos, ms);
    ctc_kernel<<<CTC_BLOCKS, 256>>>(x, target, ilen, tlen);
    reduce1_kernel<<<R1_BLOCKS, 256>>>();
    reduce2_kernel<<<1, 256>>>((float*)d_out);
}